// round 2
// baseline (speedup 1.0000x reference)
#include <cuda_runtime.h>
#include <cstddef>

// Problem constants (from reference setup_inputs: B=64,T=2048,D=128,K=1024)
#define Dm     128
#define Kc     1024
#define Nmax   131072
#define DECAYF 0.99f
#define OMDEC  0.01f        // 1 - DECAY
#define EPSV   1e-5f

// ---- device scratch (no allocations allowed) ----
__device__ int   g_idx[Nmax];
__device__ float g_esum[Kc * Dm];
__device__ float g_counts[Kc];
__device__ float g_enorm[Kc];

// ------------------------------------------------------------------
// zero the scatter accumulators (graph is replayed; must re-zero)
// ------------------------------------------------------------------
__global__ void init_kernel() {
    int i = blockIdx.x * blockDim.x + threadIdx.x;
    if (i < Kc * Dm) g_esum[i] = 0.0f;
    if (i < Kc)      g_counts[i] = 0.0f;
}

// ------------------------------------------------------------------
// per-code squared norms: one warp per code row (128 floats = 32 float4)
// ------------------------------------------------------------------
__global__ void enorm_kernel(const float* __restrict__ embed) {
    int gtid = blockIdx.x * blockDim.x + threadIdx.x;
    int warp = gtid >> 5;
    int lane = gtid & 31;
    if (warp >= Kc) return;
    float4 v = *reinterpret_cast<const float4*>(embed + (size_t)warp * Dm + lane * 4);
    float s = v.x * v.x + v.y * v.y + v.z * v.z + v.w * v.w;
    #pragma unroll
    for (int o = 16; o > 0; o >>= 1) s += __shfl_xor_sync(0xffffffffu, s, o);
    if (lane == 0) g_enorm[warp] = s;
}

// ------------------------------------------------------------------
// Fused distance-GEMM + argmax.
// Block: 128 tokens x all K codes (tiles of 128), D=128 fully resident.
// 256 threads, each owns an 8x8 (token x code) fp32 accumulator tile.
// dist = 2*dot(x,e) - ||e||^2  (the -||x||^2 row constant drops out of argmax)
// ------------------------------------------------------------------
#define TM   128
#define TKt  128
#define PAD  4
#define LDX  (TM + PAD)          // 132 floats per smem row

// dynamic smem layout: Xs[Dm][LDX] | Es[Dm][LDX] | ens[TKt]
#define SMEM_FLOATS (2 * Dm * LDX + TKt)
#define SMEM_BYTES  (SMEM_FLOATS * 4)

__global__ void __launch_bounds__(256, 1)
argmax_kernel(const float* __restrict__ x, const float* __restrict__ embed, int N)
{
    extern __shared__ float smem[];
    float* Xs  = smem;                    // transposed: Xs[d*LDX + token]
    float* Es  = smem + Dm * LDX;         // transposed: Es[d*LDX + code]
    float* ens = smem + 2 * Dm * LDX;     // ||e||^2 for the current code tile

    const int tid  = threadIdx.x;
    const int ty   = tid >> 4;            // 0..15 token group
    const int tx   = tid & 15;            // 0..15 code group
    const int tok0 = blockIdx.x * TM;

    // --- load & transpose X tile: 128 tokens x 128 dims ---
    for (int i = tid; i < TM * (Dm / 4); i += 256) {
        int t  = i >> 5;                  // token within tile (Dm/4 = 32)
        int d4 = i & 31;
        float4 v = *reinterpret_cast<const float4*>(
            x + (size_t)(tok0 + t) * Dm + d4 * 4);
        Xs[(d4 * 4 + 0) * LDX + t] = v.x;
        Xs[(d4 * 4 + 1) * LDX + t] = v.y;
        Xs[(d4 * 4 + 2) * LDX + t] = v.z;
        Xs[(d4 * 4 + 3) * LDX + t] = v.w;
    }

    float best[8];
    int   bestk[8];
    #pragma unroll
    for (int i = 0; i < 8; i++) { best[i] = -3.4e38f; bestk[i] = 0; }

    for (int kt = 0; kt < Kc; kt += TKt) {
        __syncthreads();   // Xs ready (1st iter); Es reads of prev iter done

        // --- load & transpose E tile: 128 codes x 128 dims ---
        for (int i = tid; i < TKt * (Dm / 4); i += 256) {
            int c  = i >> 5;
            int d4 = i & 31;
            float4 v = *reinterpret_cast<const float4*>(
                embed + (size_t)(kt + c) * Dm + d4 * 4);
            Es[(d4 * 4 + 0) * LDX + c] = v.x;
            Es[(d4 * 4 + 1) * LDX + c] = v.y;
            Es[(d4 * 4 + 2) * LDX + c] = v.z;
            Es[(d4 * 4 + 3) * LDX + c] = v.w;
        }
        if (tid < TKt) ens[tid] = g_enorm[kt + tid];
        __syncthreads();

        // --- 128x128x128 register-blocked fp32 GEMM ---
        float acc[8][8];
        #pragma unroll
        for (int i = 0; i < 8; i++)
            #pragma unroll
            for (int j = 0; j < 8; j++) acc[i][j] = 0.0f;

        #pragma unroll 4
        for (int d = 0; d < Dm; d++) {
            float4 xa = *reinterpret_cast<float4*>(Xs + d * LDX + ty * 8);
            float4 xb = *reinterpret_cast<float4*>(Xs + d * LDX + ty * 8 + 4);
            float4 ea = *reinterpret_cast<float4*>(Es + d * LDX + tx * 8);
            float4 eb = *reinterpret_cast<float4*>(Es + d * LDX + tx * 8 + 4);
            float xv[8] = {xa.x, xa.y, xa.z, xa.w, xb.x, xb.y, xb.z, xb.w};
            float ev[8] = {ea.x, ea.y, ea.z, ea.w, eb.x, eb.y, eb.z, eb.w};
            #pragma unroll
            for (int i = 0; i < 8; i++)
                #pragma unroll
                for (int j = 0; j < 8; j++)
                    acc[i][j] = fmaf(xv[i], ev[j], acc[i][j]);
        }

        // --- fold this code tile into the running argmax ---
        #pragma unroll
        for (int j = 0; j < 8; j++) {
            int   code = kt + tx * 8 + j;       // strictly increasing per thread
            float en   = ens[tx * 8 + j];
            #pragma unroll
            for (int i = 0; i < 8; i++) {
                float dv = 2.0f * acc[i][j] - en;
                if (dv > best[i]) { best[i] = dv; bestk[i] = code; }  // first-max kept
            }
        }
    }

    __syncthreads();
    // --- cross-thread reduction over tx (16 partials per token); reuse Es ---
    float* rv = Es;                              // [TM][16] floats
    int*   rk = reinterpret_cast<int*>(Es + TM * 16);  // [TM][16] ints
    #pragma unroll
    for (int i = 0; i < 8; i++) {
        int t = ty * 8 + i;
        rv[t * 16 + tx] = best[i];
        rk[t * 16 + tx] = bestk[i];
    }
    __syncthreads();
    if (tid < TM) {
        float bv = rv[tid * 16];
        int   bk = rk[tid * 16];
        #pragma unroll
        for (int j = 1; j < 16; j++) {
            float v  = rv[tid * 16 + j];
            int   k2 = rk[tid * 16 + j];
            if (v > bv || (v == bv && k2 < bk)) { bv = v; bk = k2; }  // jax: first max
        }
        g_idx[tok0 + tid] = bk;
    }
}

// ------------------------------------------------------------------
// quantized gather + embed_ind write + EMA scatter-adds (counts, embed_sum)
// one thread per (token, dim) element
// ------------------------------------------------------------------
__global__ void scatter_gather_kernel(const float* __restrict__ x,
                                      const float* __restrict__ embed,
                                      float* __restrict__ outq,
                                      float* __restrict__ outind,
                                      int N)
{
    int gid = blockIdx.x * blockDim.x + threadIdx.x;
    if (gid >= N * Dm) return;
    int n = gid >> 7;
    int d = gid & 127;
    int k = g_idx[n];
    outq[gid] = embed[(size_t)k * Dm + d];
    atomicAdd(&g_esum[(size_t)k * Dm + d], x[gid]);
    if (d == 0) {
        outind[n] = (float)k;
        atomicAdd(&g_counts[k], 1.0f);
    }
}

// ------------------------------------------------------------------
// EMA finalize: new_cluster_size, laplace smoothing, new_embed_avg, new_embed
// single block, K=1024 threads
// ------------------------------------------------------------------
__global__ void __launch_bounds__(1024)
finalize_kernel(const float* __restrict__ embed_avg,
                const float* __restrict__ cluster_size,
                float* __restrict__ out_ne,
                float* __restrict__ out_ncs,
                float* __restrict__ out_nea)
{
    __shared__ float ssum[32];
    __shared__ float smoothed[Kc];
    __shared__ float s_total;

    int tid  = threadIdx.x;
    int lane = tid & 31;

    float ncs = cluster_size[tid] * DECAYF + OMDEC * g_counts[tid];
    out_ncs[tid] = ncs;

    float s = ncs;
    #pragma unroll
    for (int o = 16; o > 0; o >>= 1) s += __shfl_xor_sync(0xffffffffu, s, o);
    if (lane == 0) ssum[tid >> 5] = s;
    __syncthreads();
    if (tid < 32) {
        float v = ssum[tid];
        #pragma unroll
        for (int o = 16; o > 0; o >>= 1) v += __shfl_xor_sync(0xffffffffu, v, o);
        if (tid == 0) s_total = v;
    }
    __syncthreads();
    float total = s_total;

    smoothed[tid] = (ncs + EPSV) / (total + (float)Kc * EPSV) * total;
    __syncthreads();

    for (int i = tid; i < Kc * Dm; i += 1024) {
        float nea = embed_avg[i] * DECAYF + OMDEC * g_esum[i];
        out_nea[i] = nea;
        out_ne[i]  = nea / smoothed[i >> 7];
    }
}

// ------------------------------------------------------------------
// launch
// inputs: 0=x [N,128] f32, 1=embed [1024,128] f32, 2=embed_avg [1024,128] f32,
//         3=cluster_size [1024] f32
// outputs (concatenated f32, reference return order):
//   quantized [N*128] | embed_ind [N] | new_embed [K*128] |
//   new_cluster_size [K] | new_embed_avg [K*128]
// ------------------------------------------------------------------
extern "C" void kernel_launch(void* const* d_in, const int* in_sizes, int n_in,
                              void* d_out, int out_size)
{
    const float* x     = (const float*)d_in[0];
    const float* embed = (const float*)d_in[1];
    const float* eavg  = (const float*)d_in[2];
    const float* csz   = (const float*)d_in[3];
    float* out = (float*)d_out;

    int N = in_sizes[0] / Dm;

    size_t o_ind = (size_t)N * Dm;
    size_t o_ne  = o_ind + N;
    size_t o_ncs = o_ne + (size_t)Kc * Dm;
    size_t o_nea = o_ncs + Kc;

    cudaFuncSetAttribute(argmax_kernel,
                         cudaFuncAttributeMaxDynamicSharedMemorySize, SMEM_BYTES);

    init_kernel<<<(Kc * Dm + 255) / 256, 256>>>();
    enorm_kernel<<<(Kc * 32 + 255) / 256, 256>>>(embed);
    argmax_kernel<<<N / TM, 256, SMEM_BYTES>>>(x, embed, N);
    scatter_gather_kernel<<<(N * Dm + 255) / 256, 256>>>(
        x, embed, out, out + o_ind, N);
    finalize_kernel<<<1, 1024>>>(eavg, csz, out + o_ne, out + o_ncs, out + o_nea);
}